// round 3
// baseline (speedup 1.0000x reference)
#include <cuda_runtime.h>
#include <math_constants.h>

#define N_TOK   32768
#define MEM     2000
#define MP      2048
#define KDIM    512
#define HW      1024
#define SHRINKT 0.0025f
#define EPSV    1e-12f
#define Y_ELEMS 16777216u   /* 32*512*32*32 */

__device__ float g_scores[(size_t)N_TOK * MP];

__device__ __forceinline__ unsigned long long pack2(float x) {
    unsigned long long r; unsigned xi = __float_as_uint(x);
    asm("mov.b64 %0, {%1, %1};" : "=l"(r) : "r"(xi));
    return r;
}
__device__ __forceinline__ void ffma2(unsigned long long& d, unsigned long long a, unsigned long long b) {
    asm("fma.rn.f32x2 %0, %1, %2, %0;" : "+l"(d) : "l"(a), "l"(b));
}

// ---------------- Kernel A: S = Xf @ W^T  (fp32, f32x2-packed SGEMM) ----------------
// Xf[t][c] = x[b][c][hw], t = b*1024 + hw.  Output to g_scores, row stride 2048.
__global__ __launch_bounds__(256) void gemm1_kernel(const float* __restrict__ x,
                                                    const float* __restrict__ w) {
    __shared__ float As[16][128];
    __shared__ float Bs[16][132];

    const int tid = threadIdx.x;
    const int n0 = blockIdx.x * 128;
    const int t0 = blockIdx.y * 128;
    const int b   = t0 >> 10;
    const int hw0 = t0 & 1023;
    const float* xb = x + (size_t)b * KDIM * HW + hw0;

    const int tx = tid & 15, ty = tid >> 4;

    const int ak  = tid >> 5;   // 0..7
    const int atq = tid & 31;   // 0..31
    int bn[2], bkq[2];
#pragma unroll
    for (int l = 0; l < 2; ++l) { int lin = tid + 256 * l; bn[l] = lin >> 2; bkq[l] = lin & 3; }

    float4 aR[2], bR[2];

    auto loadG = [&](int kb) {
        const int k0 = kb * 16;
#pragma unroll
        for (int p = 0; p < 2; ++p)
            aR[p] = *reinterpret_cast<const float4*>(xb + (size_t)(k0 + ak + p * 8) * HW + atq * 4);
#pragma unroll
        for (int l = 0; l < 2; ++l) {
            int n = n0 + bn[l];
            if (n < MEM) bR[l] = *reinterpret_cast<const float4*>(w + (size_t)n * KDIM + k0 + bkq[l] * 4);
            else         bR[l] = make_float4(0.f, 0.f, 0.f, 0.f);
        }
    };
    auto storeS = [&]() {
#pragma unroll
        for (int p = 0; p < 2; ++p)
            *reinterpret_cast<float4*>(&As[ak + p * 8][atq * 4]) = aR[p];
#pragma unroll
        for (int l = 0; l < 2; ++l) {
            Bs[bkq[l] * 4 + 0][bn[l]] = bR[l].x;
            Bs[bkq[l] * 4 + 1][bn[l]] = bR[l].y;
            Bs[bkq[l] * 4 + 2][bn[l]] = bR[l].z;
            Bs[bkq[l] * 4 + 3][bn[l]] = bR[l].w;
        }
    };

    unsigned long long acc[8][4];
#pragma unroll
    for (int i = 0; i < 8; ++i)
#pragma unroll
        for (int jp = 0; jp < 4; ++jp) acc[i][jp] = 0ULL;

    loadG(0);
    storeS();
    __syncthreads();

    for (int kb = 0; kb < 32; ++kb) {
        if (kb < 31) loadG(kb + 1);
#pragma unroll
        for (int k = 0; k < 16; ++k) {
            float4 a0 = *reinterpret_cast<const float4*>(&As[k][ty * 8]);
            float4 a1 = *reinterpret_cast<const float4*>(&As[k][ty * 8 + 4]);
            union { float4 f; unsigned long long u[2]; } b0, b1;
            b0.f = *reinterpret_cast<const float4*>(&Bs[k][tx * 8]);
            b1.f = *reinterpret_cast<const float4*>(&Bs[k][tx * 8 + 4]);
            float av[8] = {a0.x, a0.y, a0.z, a0.w, a1.x, a1.y, a1.z, a1.w};
#pragma unroll
            for (int i = 0; i < 8; ++i) {
                unsigned long long a2 = pack2(av[i]);
                ffma2(acc[i][0], a2, b0.u[0]);
                ffma2(acc[i][1], a2, b0.u[1]);
                ffma2(acc[i][2], a2, b1.u[0]);
                ffma2(acc[i][3], a2, b1.u[1]);
            }
        }
        if (kb < 31) { __syncthreads(); storeS(); __syncthreads(); }
    }

#pragma unroll
    for (int i = 0; i < 8; ++i) {
        float* dst = g_scores + (size_t)(t0 + ty * 8 + i) * MP + n0 + tx * 8;
        union { unsigned long long u; float2 f; } c;
#pragma unroll
        for (int jp = 0; jp < 4; ++jp) { c.u = acc[i][jp]; *reinterpret_cast<float2*>(dst + jp * 2) = c.f; }
    }
}

// ---------------- Kernel B: softmax + hard-shrink + renorm + sparse y, NCHW writes ----------------
// 1 block = 128 contiguous-hw tokens of one batch image. 256 threads (8 warps), warp-per-token.
__global__ __launch_bounds__(256) void mem_post_kernel(const float* __restrict__ w,
                                                       float* __restrict__ out) {
    __shared__ float s_mx[128], s_sm[128];
    __shared__ int   s_cnt[128];
    __shared__ int   s_pm[128][24];
    __shared__ float s_pv[128][24];
    __shared__ float s_y[8][512];

    const int tid = threadIdx.x, lane = tid & 31, wid = tid >> 5;
    const int t0  = blockIdx.x * 128;
    const int b   = t0 >> 10;
    const int hw0 = t0 & 1023;

    // Phase 1: per-token online max + sumexp (warp per token)
    for (int tg = 0; tg < 16; ++tg) {
        const int j = tg * 8 + wid;
        const float* row = g_scores + (size_t)(t0 + j) * MP;
        float mx = -CUDART_INF_F, sm = 0.f;
        for (int m = lane; m < MEM; m += 32) {
            float z = row[m];
            if (z > mx) { sm = sm * expf(mx - z) + 1.f; mx = z; }
            else        { sm += expf(z - mx); }
        }
#pragma unroll
        for (int off = 16; off; off >>= 1) {
            float mo = __shfl_xor_sync(0xffffffffu, mx, off);
            float so = __shfl_xor_sync(0xffffffffu, sm, off);
            float M  = fmaxf(mx, mo);
            sm = sm * expf(mx - M) + so * expf(mo - M);
            mx = M;
        }
        if (lane == 0) { s_mx[j] = mx; s_sm[j] = sm; }
    }
    __syncthreads();

    // Phase 2: survivors (att > thresh), deterministic ballot compaction, ordered by m
    for (int tg = 0; tg < 16; ++tg) {
        const int j = tg * 8 + wid;
        const float* row = g_scores + (size_t)(t0 + j) * MP;
        const float mx = s_mx[j], sum = s_sm[j];
        const float zth = mx + logf(0.999f * SHRINKT * sum);  // conservative pre-filter
        int base = 0;
        for (int m0 = 0; m0 < MEM; m0 += 32) {
            const int m = m0 + lane;
            bool cand = false; float v = 0.f;
            if (m < MEM) {
                float z = row[m];
                if (z > zth) {
                    float e   = expf(z - mx);
                    float att = e / sum;           // IEEE div, matches reference
                    float d   = att - SHRINKT;
                    if (d > 0.f) { v = d * att / (d + EPSV); cand = true; }
                }
            }
            unsigned ball = __ballot_sync(0xffffffffu, cand);
            if (cand) {
                int pos = base + __popc(ball & ((1u << lane) - 1u));
                if (pos < 24) { s_pm[j][pos] = m; s_pv[j][pos] = v; }
            }
            base += __popc(ball);
        }
        if (lane == 0) s_cnt[j] = base < 24 ? base : 24;
    }
    __syncthreads();

    // Phase 2.5: L1 norm over survivors, rescale in place
    for (int tg = 0; tg < 16; ++tg) {
        const int j = tg * 8 + wid;
        const int c = s_cnt[j];
        float v = (lane < c) ? s_pv[j][lane] : 0.f;
        float nrm = v;
#pragma unroll
        for (int off = 16; off; off >>= 1) nrm += __shfl_xor_sync(0xffffffffu, nrm, off);
        float D = fmaxf(nrm, EPSV);
        if (lane < c) s_pv[j][lane] = v / D;
    }
    __syncthreads();

    // Phase 3: att output (NCHW): zero-fill full 2000 x 128 region, then scatter survivors
    float* attB = out + (size_t)Y_ELEMS + (size_t)b * MEM * HW + hw0;
    const float4 z4 = make_float4(0.f, 0.f, 0.f, 0.f);
    for (int idx = tid; idx < MEM * 32; idx += 256) {
        int m = idx >> 5, q = idx & 31;
        *reinterpret_cast<float4*>(attB + (size_t)m * HW + q * 4) = z4;
    }
    __syncthreads();
    for (int idx = tid; idx < 128 * 24; idx += 256) {
        int j = idx / 24, p = idx - j * 24;
        if (p < s_cnt[j]) attB[(size_t)s_pm[j][p] * HW + j] = s_pv[j][p];
    }

    // Phase 4: y = att @ W via sparse gather, smem-staged NCHW write
    float* yB = out + (size_t)b * KDIM * HW + hw0;
    for (int tg = 0; tg < 16; ++tg) {
        __syncthreads();
        const int j = tg * 8 + wid;
        const int c = s_cnt[j];
        float acc[16];
#pragma unroll
        for (int i = 0; i < 16; ++i) acc[i] = 0.f;
        for (int p = 0; p < c; ++p) {
            int   m = s_pm[j][p];
            float v = s_pv[j][p];
            const float* wr = w + (size_t)m * KDIM + lane;
#pragma unroll
            for (int i = 0; i < 16; ++i) acc[i] = fmaf(v, wr[i * 32], acc[i]);
        }
#pragma unroll
        for (int i = 0; i < 16; ++i) s_y[wid][lane + i * 32] = acc[i];
        __syncthreads();
        for (int idx = tid; idx < 8 * 512; idx += 256) {
            int cch = idx >> 3, jj = idx & 7;
            yB[(size_t)cch * HW + tg * 8 + jj] = s_y[jj][cch];
        }
    }
}

extern "C" void kernel_launch(void* const* d_in, const int* in_sizes, int n_in,
                              void* d_out, int out_size) {
    const float* x = (const float*)d_in[0];
    const float* w = (const float*)d_in[1];
    if (n_in >= 2 && in_sizes[0] == MEM * KDIM) {  // defensive input-order swap
        x = (const float*)d_in[1];
        w = (const float*)d_in[0];
    }
    float* out = (float*)d_out;

    dim3 gA(16, 256);            // 2048/128 slot tiles x 32768/128 token tiles
    gemm1_kernel<<<gA, 256>>>(x, w);
    mem_post_kernel<<<256, 256>>>(w, out);
}

// round 14
// speedup vs baseline: 1.5369x; 1.5369x over previous
#include <cuda_runtime.h>
#include <math_constants.h>
#include <cstdint>

#define N_TOK   32768
#define MEM     2000
#define MP      2048
#define KDIM    512
#define HW      1024
#define BATCH   32
#define SHRINKT 0.0025f
#define EPSV    1e-12f
#define Y_ELEMS 16777216u   /* 32*512*32*32 */
#define PCAP    24

__device__ float g_scores[(size_t)N_TOK * MP];
__device__ float g_wT[(size_t)KDIM * MP];      // [k][n], zero-padded for n >= MEM

// ---------------------------------------------------------------- helpers
__device__ __forceinline__ uint32_t smem_u32(const void* p) {
    uint32_t a;
    asm("{ .reg .u64 t; cvta.to.shared.u64 t, %1; cvt.u32.u64 %0, t; }" : "=r"(a) : "l"(p));
    return a;
}
#define CPA16(dst, src)  asm volatile("cp.async.cg.shared.global [%0], [%1], 16;" :: "r"(dst), "l"(src))
#define CPA_COMMIT()     asm volatile("cp.async.commit_group;" ::: "memory")
#define CPA_WAIT1()      asm volatile("cp.async.wait_group 1;" ::: "memory")
#define CPA_WAIT0()      asm volatile("cp.async.wait_group 0;" ::: "memory")

__device__ __forceinline__ unsigned long long pack2(float x) {
    unsigned long long r; unsigned xi = __float_as_uint(x);
    asm("mov.b64 %0, {%1, %1};" : "=l"(r) : "r"(xi));
    return r;
}
__device__ __forceinline__ void ffma2(unsigned long long& d, unsigned long long a, unsigned long long b) {
    asm("fma.rn.f32x2 %0, %1, %2, %0;" : "+l"(d) : "l"(a), "l"(b));
}

// ---------------------------------------------------------------- prep: wT[k][n] = w[n][k], zero-padded
__global__ __launch_bounds__(256) void prep_wT_kernel(const float* __restrict__ w) {
    __shared__ float tile[32][33];
    const int tx = threadIdx.x, ty = threadIdx.y;      // (32,8)
    const int n0 = blockIdx.x * 32, k0 = blockIdx.y * 32;
#pragma unroll
    for (int i = 0; i < 4; ++i) {
        int n = n0 + ty + 8 * i;
        tile[ty + 8 * i][tx] = (n < MEM) ? w[(size_t)n * KDIM + k0 + tx] : 0.f;
    }
    __syncthreads();
#pragma unroll
    for (int i = 0; i < 4; ++i)
        g_wT[(size_t)(k0 + ty + 8 * i) * MP + n0 + tx] = tile[tx][ty + 8 * i];
}

// ---------------------------------------------------------------- fp32 f32x2 SGEMM, 3-stage cp.async
// S = Xf @ W^T. Per-output accumulation: single fp32 FMA chain, k ascending 0..511
// (bitwise identical to the R3 kernel that passed at rel_err 6.87e-7).
#define GA_STRIDE 8192                 /* bytes per A stage: 16*128*4 */
#define GB_STRIDE 8448                 /* bytes per B stage: 16*132*4 */
#define GB_BASE   (3 * GA_STRIDE)
#define GSM_TOTAL (3 * GA_STRIDE + 3 * GB_STRIDE)   /* 49920 B */

__global__ __launch_bounds__(256, 2) void gemm_f32_kernel(const float* __restrict__ x) {
    extern __shared__ __align__(16) char gsm[];
    const uint32_t sb = smem_u32(gsm);

    const int tid = threadIdx.x;
    const int n0 = blockIdx.x * 128;
    const int t0 = blockIdx.y * 128;
    const int b   = t0 >> 10;
    const int hw0 = t0 & 1023;
    const float* xb = x + (size_t)b * KDIM * HW + hw0;

    const int tx = tid & 15, ty = tid >> 4;

    // cp.async chunk mapping: 512 x 16B chunks per stage per array, 2 per thread
    auto cp_stage = [&](int kb, int s) {
        const int k0 = kb * 16;
#pragma unroll
        for (int j = 0; j < 2; ++j) {
            const int c = tid + 256 * j;
            const int r = c >> 5, q = c & 31;
            CPA16(sb + s * GA_STRIDE + r * 512 + q * 16,
                  xb + (size_t)(k0 + r) * HW + q * 4);
            CPA16(sb + GB_BASE + s * GB_STRIDE + r * 528 + q * 16,
                  g_wT + (size_t)(k0 + r) * MP + n0 + q * 4);
        }
        CPA_COMMIT();
    };

    unsigned long long acc[8][4];
#pragma unroll
    for (int i = 0; i < 8; ++i)
#pragma unroll
        for (int jp = 0; jp < 4; ++jp) acc[i][jp] = 0ULL;

    cp_stage(0, 0);
    cp_stage(1, 1);

#pragma unroll 1
    for (int kb = 0; kb < 32; ++kb) {
        if (kb + 2 <= 31) CPA_WAIT1(); else CPA_WAIT0();
        __syncthreads();
        if (kb + 2 < 32) cp_stage(kb + 2, (kb + 2) % 3);

        const int s = kb % 3;
        const float* As = reinterpret_cast<const float*>(gsm + s * GA_STRIDE);
        const float* Bs = reinterpret_cast<const float*>(gsm + GB_BASE + s * GB_STRIDE);
#pragma unroll
        for (int k = 0; k < 16; ++k) {
            float4 a0 = *reinterpret_cast<const float4*>(As + k * 128 + ty * 8);
            float4 a1 = *reinterpret_cast<const float4*>(As + k * 128 + ty * 8 + 4);
            union { float4 f; unsigned long long u[2]; } b0, b1;
            b0.f = *reinterpret_cast<const float4*>(Bs + k * 132 + tx * 8);
            b1.f = *reinterpret_cast<const float4*>(Bs + k * 132 + tx * 8 + 4);
            float av[8] = {a0.x, a0.y, a0.z, a0.w, a1.x, a1.y, a1.z, a1.w};
#pragma unroll
            for (int i = 0; i < 8; ++i) {
                unsigned long long a2 = pack2(av[i]);
                ffma2(acc[i][0], a2, b0.u[0]);
                ffma2(acc[i][1], a2, b0.u[1]);
                ffma2(acc[i][2], a2, b1.u[0]);
                ffma2(acc[i][3], a2, b1.u[1]);
            }
        }
    }

#pragma unroll
    for (int i = 0; i < 8; ++i) {
        float* dst = g_scores + (size_t)(t0 + ty * 8 + i) * MP + n0 + tx * 8;
        union { unsigned long long u; float2 f; } c;
#pragma unroll
        for (int jp = 0; jp < 4; ++jp) { c.u = acc[i][jp]; *reinterpret_cast<float2*>(dst + jp * 2) = c.f; }
    }
}

// ---------------------------------------------------------------- att zero-fill
__global__ __launch_bounds__(256) void fill_att_kernel(float* __restrict__ out) {
    float4* p = reinterpret_cast<float4*>(out + Y_ELEMS);
    const size_t n = (size_t)BATCH * MEM * HW / 4;
    const float4 z = make_float4(0.f, 0.f, 0.f, 0.f);
    for (size_t i = (size_t)blockIdx.x * blockDim.x + threadIdx.x; i < n;
         i += (size_t)gridDim.x * blockDim.x)
        p[i] = z;
}

// ---------------------------------------------------------------- post kernel
// R3's per-warp numerics VERBATIM (online max/sum, 0.999 pre-filter, att=e/sum,
// shrink, butterfly renorm, PCAP=24); restructured to 4096 blocks x warp-per-token
// with smem row staging (staging changes no values).
__global__ __launch_bounds__(256) void post_kernel(const float* __restrict__ w,
                                                   float* __restrict__ out) {
    extern __shared__ float srow[];                 // [8][2000]
    __shared__ int   s_pm[8][PCAP];
    __shared__ float s_pv[8][PCAP];
    __shared__ float s_y[8][512];

    const int tid = threadIdx.x, lane = tid & 31, wid = tid >> 5;
    const int t0 = blockIdx.x * 8;
    const int b = t0 >> 10, hw0 = t0 & 1023;

    const float* grow = g_scores + (size_t)(t0 + wid) * MP;
    float* row = srow + wid * 2000;

    // stage row to smem (values unchanged)
    for (int i = lane; i < 500; i += 32)
        *reinterpret_cast<float4*>(row + i * 4) =
            *reinterpret_cast<const float4*>(grow + i * 4);
    __syncwarp();

    // phase 1 (R3 verbatim): per-token online max + sumexp
    float mx = -CUDART_INF_F, sm = 0.f;
    for (int m = lane; m < MEM; m += 32) {
        float z = row[m];
        if (z > mx) { sm = sm * expf(mx - z) + 1.f; mx = z; }
        else        { sm += expf(z - mx); }
    }
#pragma unroll
    for (int off = 16; off; off >>= 1) {
        float mo = __shfl_xor_sync(0xffffffffu, mx, off);
        float so = __shfl_xor_sync(0xffffffffu, sm, off);
        float M  = fmaxf(mx, mo);
        sm = sm * expf(mx - M) + so * expf(mo - M);
        mx = M;
    }
    const float sum = sm;

    // phase 2 (R3 verbatim): survivors, deterministic ballot compaction
    const float zth = mx + logf(0.999f * SHRINKT * sum);
    int base = 0;
    for (int m0 = 0; m0 < MEM; m0 += 32) {
        const int m = m0 + lane;
        bool cand = false; float v = 0.f;
        if (m < MEM) {
            float z = row[m];
            if (z > zth) {
                float e   = expf(z - mx);
                float att = e / sum;
                float d   = att - SHRINKT;
                if (d > 0.f) { v = d * att / (d + EPSV); cand = true; }
            }
        }
        unsigned ball = __ballot_sync(0xffffffffu, cand);
        if (cand) {
            int pos = base + __popc(ball & ((1u << lane) - 1u));
            if (pos < PCAP) { s_pm[wid][pos] = m; s_pv[wid][pos] = v; }
        }
        base += __popc(ball);
    }
    const int cnt = base < PCAP ? base : PCAP;
    __syncwarp();

    // phase 2.5 (R3 verbatim): L1 renorm over survivors
    {
        float v = (lane < cnt) ? s_pv[wid][lane] : 0.f;
        float nrm = v;
#pragma unroll
        for (int off = 16; off; off >>= 1) nrm += __shfl_xor_sync(0xffffffffu, nrm, off);
        float D = fmaxf(nrm, EPSV);
        if (lane < cnt) s_pv[wid][lane] = v / D;
    }
    __syncwarp();

    // scatter att (region pre-zeroed by fill_att_kernel)
    float* attB = out + Y_ELEMS + (size_t)b * MEM * HW + hw0;
    for (int p = lane; p < cnt; p += 32)
        attB[(size_t)s_pm[wid][p] * HW + wid] = s_pv[wid][p];

    // phase 4 (R3 verbatim math): y = att @ W via survivor gather
    float acc[16];
#pragma unroll
    for (int i = 0; i < 16; ++i) acc[i] = 0.f;
    for (int p = 0; p < cnt; ++p) {
        const int m = s_pm[wid][p];
        const float vv = s_pv[wid][p];
        const float* wr = w + (size_t)m * KDIM + lane;
#pragma unroll
        for (int i = 0; i < 16; ++i) acc[i] = fmaf(vv, wr[i * 32], acc[i]);
    }
#pragma unroll
    for (int i = 0; i < 16; ++i) s_y[wid][lane + 32 * i] = acc[i];
    __syncthreads();

    float* yB = out + (size_t)b * KDIM * HW + hw0;
    for (int idx = tid; idx < 8 * KDIM; idx += 256) {
        int ch = idx >> 3, j = idx & 7;
        yB[(size_t)ch * HW + j] = s_y[j][ch];
    }
}

// ---------------------------------------------------------------- launch
extern "C" void kernel_launch(void* const* d_in, const int* in_sizes, int n_in,
                              void* d_out, int out_size) {
    const float* x = (const float*)d_in[0];
    const float* w = (const float*)d_in[1];
    if (n_in >= 2 && in_sizes[0] == MEM * KDIM) {  // defensive input-order swap
        x = (const float*)d_in[1];
        w = (const float*)d_in[0];
    }
    float* out = (float*)d_out;

    cudaFuncSetAttribute(gemm_f32_kernel, cudaFuncAttributeMaxDynamicSharedMemorySize,
                         GSM_TOTAL);
    cudaFuncSetAttribute(post_kernel, cudaFuncAttributeMaxDynamicSharedMemorySize,
                         8 * 2000 * (int)sizeof(float));

    prep_wT_kernel<<<dim3(64, 16), dim3(32, 8)>>>(w);
    gemm_f32_kernel<<<dim3(16, 256), 256, GSM_TOTAL>>>(x);
    fill_att_kernel<<<4096, 256>>>(out);
    post_kernel<<<4096, 256, 8 * 2000 * sizeof(float)>>>(w, out);
}

// round 15
// speedup vs baseline: 1.6645x; 1.0830x over previous
#include <cuda_runtime.h>
#include <math_constants.h>
#include <cstdint>

#define N_TOK   32768
#define MEM     2000
#define MP      2048
#define KDIM    512
#define HW      1024
#define BATCH   32
#define SHRINKT 0.0025f
#define EPSV    1e-12f
#define Y_ELEMS 16777216u   /* 32*512*32*32 */
#define PCAP    24

__device__ float g_scores[(size_t)N_TOK * MP];
__device__ float g_wT[(size_t)KDIM * MP];      // [k][n], zero-padded for n >= MEM

// ---------------------------------------------------------------- helpers
__device__ __forceinline__ uint32_t smem_u32(const void* p) {
    uint32_t a;
    asm("{ .reg .u64 t; cvta.to.shared.u64 t, %1; cvt.u32.u64 %0, t; }" : "=r"(a) : "l"(p));
    return a;
}
#define CPA16(dst, src)  asm volatile("cp.async.cg.shared.global [%0], [%1], 16;" :: "r"(dst), "l"(src))
#define CPA_COMMIT()     asm volatile("cp.async.commit_group;" ::: "memory")
#define CPA_WAIT1()      asm volatile("cp.async.wait_group 1;" ::: "memory")
#define CPA_WAIT0()      asm volatile("cp.async.wait_group 0;" ::: "memory")

__device__ __forceinline__ unsigned long long pack2(float x) {
    unsigned long long r; unsigned xi = __float_as_uint(x);
    asm("mov.b64 %0, {%1, %1};" : "=l"(r) : "r"(xi));
    return r;
}
__device__ __forceinline__ void ffma2(unsigned long long& d, unsigned long long a, unsigned long long b) {
    asm("fma.rn.f32x2 %0, %1, %2, %0;" : "+l"(d) : "l"(a), "l"(b));
}

// ---------------------------------------------------------------- prep: wT[k][n] = w[n][k], zero-padded
__global__ __launch_bounds__(256) void prep_wT_kernel(const float* __restrict__ w) {
    __shared__ float tile[32][33];
    const int tx = threadIdx.x, ty = threadIdx.y;      // (32,8)
    const int n0 = blockIdx.x * 32, k0 = blockIdx.y * 32;
#pragma unroll
    for (int i = 0; i < 4; ++i) {
        int n = n0 + ty + 8 * i;
        tile[ty + 8 * i][tx] = (n < MEM) ? w[(size_t)n * KDIM + k0 + tx] : 0.f;
    }
    __syncthreads();
#pragma unroll
    for (int i = 0; i < 4; ++i)
        g_wT[(size_t)(k0 + ty + 8 * i) * MP + n0 + tx] = tile[tx][ty + 8 * i];
}

// ---------------------------------------------------------------- fp32 f32x2 SGEMM, BK=32, 3-stage cp.async
// S = Xf @ W^T. Per-output accumulation: single fp32 FMA chain, k ascending 0..511
// (bitwise identical to R3/R14 kernels; staging/tiling changes no values).
#define GA_STRIDE 16384                /* bytes per A stage: 32*128*4 */
#define GB_STRIDE 16896                /* bytes per B stage: 32*132*4 */
#define GB_BASE   (3 * GA_STRIDE)
#define GSM_TOTAL (3 * GA_STRIDE + 3 * GB_STRIDE)   /* 99840 B */

__global__ __launch_bounds__(256, 2) void gemm_f32_kernel(const float* __restrict__ x) {
    extern __shared__ __align__(16) char gsm[];
    const uint32_t sb = smem_u32(gsm);

    const int tid = threadIdx.x;
    const int n0 = blockIdx.x * 128;
    const int t0 = blockIdx.y * 128;
    const int b   = t0 >> 10;
    const int hw0 = t0 & 1023;
    const float* xb = x + (size_t)b * KDIM * HW + hw0;

    const int tx = tid & 15, ty = tid >> 4;

    // cp.async chunk mapping: 1024 x 16B chunks per stage per array, 4 per thread
    auto cp_stage = [&](int kb, int s) {
        const int k0 = kb * 32;
#pragma unroll
        for (int j = 0; j < 4; ++j) {
            const int c = tid + 256 * j;
            const int r = c >> 5, q = c & 31;
            CPA16(sb + s * GA_STRIDE + r * 512 + q * 16,
                  xb + (size_t)(k0 + r) * HW + q * 4);
            CPA16(sb + GB_BASE + s * GB_STRIDE + r * 528 + q * 16,
                  g_wT + (size_t)(k0 + r) * MP + n0 + q * 4);
        }
        CPA_COMMIT();
    };

    unsigned long long acc[8][4];
#pragma unroll
    for (int i = 0; i < 8; ++i)
#pragma unroll
        for (int jp = 0; jp < 4; ++jp) acc[i][jp] = 0ULL;

    cp_stage(0, 0);
    cp_stage(1, 1);

#pragma unroll 1
    for (int kb = 0; kb < 16; ++kb) {
        if (kb + 2 <= 15) CPA_WAIT1(); else CPA_WAIT0();
        __syncthreads();
        if (kb + 2 < 16) cp_stage(kb + 2, (kb + 2) % 3);

        const int s = kb % 3;
        const float* As = reinterpret_cast<const float*>(gsm + s * GA_STRIDE);
        const float* Bs = reinterpret_cast<const float*>(gsm + GB_BASE + s * GB_STRIDE);
#pragma unroll 16
        for (int k = 0; k < 32; ++k) {
            float4 a0 = *reinterpret_cast<const float4*>(As + k * 128 + ty * 8);
            float4 a1 = *reinterpret_cast<const float4*>(As + k * 128 + ty * 8 + 4);
            union { float4 f; unsigned long long u[2]; } b0, b1;
            b0.f = *reinterpret_cast<const float4*>(Bs + k * 132 + tx * 8);
            b1.f = *reinterpret_cast<const float4*>(Bs + k * 132 + tx * 8 + 4);
            float av[8] = {a0.x, a0.y, a0.z, a0.w, a1.x, a1.y, a1.z, a1.w};
#pragma unroll
            for (int i = 0; i < 8; ++i) {
                unsigned long long a2 = pack2(av[i]);
                ffma2(acc[i][0], a2, b0.u[0]);
                ffma2(acc[i][1], a2, b0.u[1]);
                ffma2(acc[i][2], a2, b1.u[0]);
                ffma2(acc[i][3], a2, b1.u[1]);
            }
        }
    }

#pragma unroll
    for (int i = 0; i < 8; ++i) {
        float* dst = g_scores + (size_t)(t0 + ty * 8 + i) * MP + n0 + tx * 8;
        union { unsigned long long u; float2 f; } c;
#pragma unroll
        for (int jp = 0; jp < 4; ++jp) { c.u = acc[i][jp]; *reinterpret_cast<float2*>(dst + jp * 2) = c.f; }
    }
}

// ---------------------------------------------------------------- att zero-fill
__global__ __launch_bounds__(256) void fill_att_kernel(float* __restrict__ out) {
    float4* p = reinterpret_cast<float4*>(out + Y_ELEMS);
    const size_t n = (size_t)BATCH * MEM * HW / 4;
    const float4 z = make_float4(0.f, 0.f, 0.f, 0.f);
    for (size_t i = (size_t)blockIdx.x * blockDim.x + threadIdx.x; i < n;
         i += (size_t)gridDim.x * blockDim.x)
        p[i] = z;
}

// ---------------------------------------------------------------- post kernel
// R3's per-warp numerics VERBATIM; 4096 blocks x warp-per-token with smem row
// staging. y-staging buffer ALIASES the score row region (dead after phase 2),
// cutting smem 82->66 KB -> 3 blocks/SM.
__global__ __launch_bounds__(256) void post_kernel(const float* __restrict__ w,
                                                   float* __restrict__ out) {
    extern __shared__ float srow[];                 // [8][2000]; reused for y staging
    __shared__ int   s_pm[8][PCAP];
    __shared__ float s_pv[8][PCAP];

    const int tid = threadIdx.x, lane = tid & 31, wid = tid >> 5;
    const int t0 = blockIdx.x * 8;
    const int b = t0 >> 10, hw0 = t0 & 1023;

    const float* grow = g_scores + (size_t)(t0 + wid) * MP;
    float* row = srow + wid * 2000;

    // stage row to smem (values unchanged)
    for (int i = lane; i < 500; i += 32)
        *reinterpret_cast<float4*>(row + i * 4) =
            *reinterpret_cast<const float4*>(grow + i * 4);
    __syncwarp();

    // phase 1 (R3 verbatim): per-token online max + sumexp
    float mx = -CUDART_INF_F, sm = 0.f;
    for (int m = lane; m < MEM; m += 32) {
        float z = row[m];
        if (z > mx) { sm = sm * expf(mx - z) + 1.f; mx = z; }
        else        { sm += expf(z - mx); }
    }
#pragma unroll
    for (int off = 16; off; off >>= 1) {
        float mo = __shfl_xor_sync(0xffffffffu, mx, off);
        float so = __shfl_xor_sync(0xffffffffu, sm, off);
        float M  = fmaxf(mx, mo);
        sm = sm * expf(mx - M) + so * expf(mo - M);
        mx = M;
    }
    const float sum = sm;

    // phase 2 (R3 verbatim): survivors, deterministic ballot compaction
    const float zth = mx + logf(0.999f * SHRINKT * sum);
    int base = 0;
    for (int m0 = 0; m0 < MEM; m0 += 32) {
        const int m = m0 + lane;
        bool cand = false; float v = 0.f;
        if (m < MEM) {
            float z = row[m];
            if (z > zth) {
                float e   = expf(z - mx);
                float att = e / sum;
                float d   = att - SHRINKT;
                if (d > 0.f) { v = d * att / (d + EPSV); cand = true; }
            }
        }
        unsigned ball = __ballot_sync(0xffffffffu, cand);
        if (cand) {
            int pos = base + __popc(ball & ((1u << lane) - 1u));
            if (pos < PCAP) { s_pm[wid][pos] = m; s_pv[wid][pos] = v; }
        }
        base += __popc(ball);
    }
    const int cnt = base < PCAP ? base : PCAP;
    __syncwarp();

    // phase 2.5 (R3 verbatim): L1 renorm over survivors
    {
        float v = (lane < cnt) ? s_pv[wid][lane] : 0.f;
        float nrm = v;
#pragma unroll
        for (int off = 16; off; off >>= 1) nrm += __shfl_xor_sync(0xffffffffu, nrm, off);
        float D = fmaxf(nrm, EPSV);
        if (lane < cnt) s_pv[wid][lane] = v / D;
    }
    __syncwarp();

    // scatter att (region pre-zeroed by fill_att_kernel)
    float* attB = out + Y_ELEMS + (size_t)b * MEM * HW + hw0;
    for (int p = lane; p < cnt; p += 32)
        attB[(size_t)s_pm[wid][p] * HW + wid] = s_pv[wid][p];

    // phase 4 (R3 verbatim math): y = att @ W via survivor gather.
    // Score row data is dead now; reuse this warp's srow region for y staging.
    float acc[16];
#pragma unroll
    for (int i = 0; i < 16; ++i) acc[i] = 0.f;
    for (int p = 0; p < cnt; ++p) {
        const int m = s_pm[wid][p];
        const float vv = s_pv[wid][p];
        const float* wr = w + (size_t)m * KDIM + lane;
#pragma unroll
        for (int i = 0; i < 16; ++i) acc[i] = fmaf(vv, wr[i * 32], acc[i]);
    }
    __syncthreads();   // all warps done reading their rows before overwrite
#pragma unroll
    for (int i = 0; i < 16; ++i) row[lane + 32 * i] = acc[i];
    __syncthreads();

    float* yB = out + (size_t)b * KDIM * HW + hw0;
    for (int idx = tid; idx < 8 * KDIM; idx += 256) {
        int ch = idx >> 3, j = idx & 7;
        yB[(size_t)ch * HW + j] = srow[j * 2000 + ch];
    }
}

// ---------------------------------------------------------------- launch
extern "C" void kernel_launch(void* const* d_in, const int* in_sizes, int n_in,
                              void* d_out, int out_size) {
    const float* x = (const float*)d_in[0];
    const float* w = (const float*)d_in[1];
    if (n_in >= 2 && in_sizes[0] == MEM * KDIM) {  // defensive input-order swap
        x = (const float*)d_in[1];
        w = (const float*)d_in[0];
    }
    float* out = (float*)d_out;

    cudaFuncSetAttribute(gemm_f32_kernel, cudaFuncAttributeMaxDynamicSharedMemorySize,
                         GSM_TOTAL);
    cudaFuncSetAttribute(post_kernel, cudaFuncAttributeMaxDynamicSharedMemorySize,
                         8 * 2000 * (int)sizeof(float));

    prep_wT_kernel<<<dim3(64, 16), dim3(32, 8)>>>(w);
    gemm_f32_kernel<<<dim3(16, 256), 256, GSM_TOTAL>>>(x);
    fill_att_kernel<<<4096, 256>>>(out);
    post_kernel<<<4096, 256, 8 * 2000 * sizeof(float)>>>(w, out);
}